// round 14
// baseline (speedup 1.0000x reference)
#include <cuda_runtime.h>
#include <cstdint>

// A is [16384, 512] fp32 row-major.
// out = (||colsum||^2 - sum(A*A)) / (n*(n-1))
#define D      512
#define D4     128
#define GRID   148                   // one CTA per SM (best-measured geometry)
#define TPB    512
#define FAST_N4 (16384 * 128)
#define SPREAD 64                    // floats between live REDG slots (256B)

// Scratch (no allocations allowed). Spread accumulators start zero and are
// re-zeroed by the final block each launch.
__device__ float        g_spread[D * SPREAD];
__device__ float        g_sqsum;
__device__ unsigned int g_count;

__device__ __forceinline__ void red_add_f32(float* p, float v) {
    asm volatile("red.relaxed.gpu.global.add.f32 [%0], %1;"
                 :: "l"(p), "f"(v) : "memory");
}

__device__ __forceinline__ unsigned int atom_inc_acqrel(unsigned int* p) {
    unsigned int old;
    asm volatile("atom.acq_rel.gpu.global.add.u32 %0, [%1], 1;"
                 : "=r"(old) : "l"(p) : "memory");
    return old;
}

__global__ void __launch_bounds__(TPB, 1)
ddc2_kernel(const float* __restrict__ A, int n_rows, float* __restrict__ out) {
    const int t  = threadIdx.x;
    const int c4 = t & (D4 - 1);     // float4 column chunk (stride % 128 == 0)
    const int rs = t >> 7;           // phase 0..3

    const float4* __restrict__ A4 = reinterpret_cast<const float4*>(A);
    const size_t N4     = (size_t)n_rows * D4;
    const size_t stride = (size_t)GRID * TPB;        // 75776
    size_t i = (size_t)blockIdx.x * TPB + t;

    float ax = 0.f, ay = 0.f, az = 0.f, aw = 0.f;
    float sq = 0.f;

    if (N4 == (size_t)FAST_N4) {
        // 27 full strides per thread + 1 predicated; MLP-8 front batches.
        #pragma unroll
        for (int b = 0; b < 3; b++) {
            float4 v[8];
            #pragma unroll
            for (int j = 0; j < 8; j++)
                v[j] = A4[i + (size_t)j * stride];
            #pragma unroll
            for (int j = 0; j < 8; j++) {
                ax += v[j].x; ay += v[j].y; az += v[j].z; aw += v[j].w;
                sq = fmaf(v[j].x, v[j].x, sq);
                sq = fmaf(v[j].y, v[j].y, sq);
                sq = fmaf(v[j].z, v[j].z, sq);
                sq = fmaf(v[j].w, v[j].w, sq);
            }
            i += 8 * stride;
        }
        {
            float4 v0 = A4[i];
            float4 v1 = A4[i + stride];
            float4 v2 = A4[i + 2 * stride];
            const size_t i3 = i + 3 * stride;
            float4 v3 = (i3 < N4) ? A4[i3] : make_float4(0.f, 0.f, 0.f, 0.f);

            ax += (v0.x + v1.x) + (v2.x + v3.x);
            ay += (v0.y + v1.y) + (v2.y + v3.y);
            az += (v0.z + v1.z) + (v2.z + v3.z);
            aw += (v0.w + v1.w) + (v2.w + v3.w);
            sq = fmaf(v0.x, v0.x, sq); sq = fmaf(v0.y, v0.y, sq);
            sq = fmaf(v0.z, v0.z, sq); sq = fmaf(v0.w, v0.w, sq);
            sq = fmaf(v1.x, v1.x, sq); sq = fmaf(v1.y, v1.y, sq);
            sq = fmaf(v1.z, v1.z, sq); sq = fmaf(v1.w, v1.w, sq);
            sq = fmaf(v2.x, v2.x, sq); sq = fmaf(v2.y, v2.y, sq);
            sq = fmaf(v2.z, v2.z, sq); sq = fmaf(v2.w, v2.w, sq);
            sq = fmaf(v3.x, v3.x, sq); sq = fmaf(v3.y, v3.y, sq);
            sq = fmaf(v3.z, v3.z, sq); sq = fmaf(v3.w, v3.w, sq);
        }
    } else {
        for (; i < N4; i += stride) {
            float4 v = A4[i];
            ax += v.x; ay += v.y; az += v.z; aw += v.w;
            sq = fmaf(v.x, v.x, sq); sq = fmaf(v.y, v.y, sq);
            sq = fmaf(v.z, v.z, sq); sq = fmaf(v.w, v.w, sq);
        }
    }

    // ---- sumsq: warp shuffle reduce; each warp leader REDs its partial
    //      (slice-spread scalar slot; 16 REDs/block, zero contention cost) ----
    #pragma unroll
    for (int off = 16; off > 0; off >>= 1)
        sq += __shfl_xor_sync(0xFFFFFFFFu, sq, off);
    if ((t & 31) == 0) red_add_f32(&g_sqsum, sq);

    // ---- combine the 4 phases via smem, then slice-spread REDG ----
    __shared__ float4 sc[4][D4];
    sc[rs][c4] = make_float4(ax, ay, az, aw);
    __syncthreads();

    if (t < D4) {
        float4 s0 = sc[0][t], s1 = sc[1][t], s2 = sc[2][t], s3 = sc[3][t];
        red_add_f32(&g_spread[(4 * t + 0) * SPREAD], (s0.x + s1.x) + (s2.x + s3.x));
        red_add_f32(&g_spread[(4 * t + 1) * SPREAD], (s0.y + s1.y) + (s2.y + s3.y));
        red_add_f32(&g_spread[(4 * t + 2) * SPREAD], (s0.z + s1.z) + (s2.z + s3.z));
        red_add_f32(&g_spread[(4 * t + 3) * SPREAD], (s0.w + s1.w) + (s2.w + s3.w));
    }

    // ---- single arrival counter; last block finalizes ----
    __syncthreads();
    __shared__ int sh_last;
    if (t == 0)
        sh_last = (atom_inc_acqrel(&g_count) == GRID - 1u);
    __syncthreads();
    if (!sh_last) return;

    {
        float c = g_spread[t * SPREAD];    // one colsum slot per thread
        g_spread[t * SPREAD] = 0.f;        // reset for next replay
        float r = c * c;

        if (t == 0) {
            r -= g_sqsum;
            g_sqsum = 0.f;
        }

        #pragma unroll
        for (int off = 16; off > 0; off >>= 1)
            r += __shfl_xor_sync(0xFFFFFFFFu, r, off);

        __shared__ float fwarp[TPB / 32];
        if ((t & 31) == 0) fwarp[t >> 5] = r;
        __syncthreads();

        if (t < 32) {
            float w = (t < TPB / 32) ? fwarp[t] : 0.f;
            #pragma unroll
            for (int off = 8; off > 0; off >>= 1)
                w += __shfl_xor_sync(0xFFFFu, w, off);
            if (t == 0) {
                double denom = (double)n_rows * (double)(n_rows - 1);
                out[0] = (float)((double)w / denom);
                g_count = 0u;              // reset for next replay
            }
        }
    }
}

extern "C" void kernel_launch(void* const* d_in, const int* in_sizes, int n_in,
                              void* d_out, int out_size) {
    const float* A = (const float*)d_in[0];
    const int n_rows = in_sizes[0] / D;   // 16384
    ddc2_kernel<<<GRID, TPB>>>(A, n_rows, (float*)d_out);
}

// round 15
// speedup vs baseline: 1.6048x; 1.6048x over previous
#include <cuda_runtime.h>
#include <cstdint>

// A is [16384, 512] fp32 row-major.
// out = (||colsum||^2 - sum(A*A)) / (n*(n-1))
#define D      512
#define D4     128
#define GRID   148                   // one CTA per SM
#define TPB    512
#define NGROUPS 37                   // 148 / 4 blocks per group
#define FAST_N4 (16384 * 128)        // total float4 elements for the fixed shape

// Scratch (no allocations allowed). Data arrays fully overwritten each
// launch; counters reset by the final block.
__device__ float        g_part[GRID * D];
__device__ float        g_sqpart[GRID];
__device__ float        g_gpart[NGROUPS * D];
__device__ float        g_gsq[NGROUPS];
__device__ unsigned int g_gcount[NGROUPS];
__device__ unsigned int g_fcount;

// Fused release-ordered fetch-add (no separate MEMBAR on the signal path).
__device__ __forceinline__ unsigned int atom_inc_acqrel(unsigned int* p) {
    unsigned int old;
    asm volatile("atom.acq_rel.gpu.global.add.u32 %0, [%1], 1;"
                 : "=r"(old) : "l"(p) : "memory");
    return old;
}

__global__ void __launch_bounds__(TPB, 1)
ddc2_kernel(const float* __restrict__ A, int n_rows, float* __restrict__ out) {
    const int t  = threadIdx.x;
    const int c4 = t & (D4 - 1);     // float4 column chunk (stride % 128 == 0 -> invariant)
    const int rs = t >> 7;           // phase 0..3

    const float4* __restrict__ A4 = reinterpret_cast<const float4*>(A);
    const size_t N4     = (size_t)n_rows * D4;
    const size_t stride = (size_t)GRID * TPB;        // 75776
    size_t i = (size_t)blockIdx.x * TPB + t;

    float ax = 0.f, ay = 0.f, az = 0.f, aw = 0.f;
    float sq = 0.f;

    if (N4 == (size_t)FAST_N4) {
        // 27 full strides for every thread + 1 predicated stride.
        // Main: 3 front-batched MLP=8 groups (24 strides).
        #pragma unroll
        for (int b = 0; b < 3; b++) {
            float4 v[8];
            #pragma unroll
            for (int j = 0; j < 8; j++)
                v[j] = A4[i + (size_t)j * stride];
            #pragma unroll
            for (int j = 0; j < 8; j++) {
                ax += v[j].x; ay += v[j].y; az += v[j].z; aw += v[j].w;
                sq = fmaf(v[j].x, v[j].x, sq);
                sq = fmaf(v[j].y, v[j].y, sq);
                sq = fmaf(v[j].z, v[j].z, sq);
                sq = fmaf(v[j].w, v[j].w, sq);
            }
            i += 8 * stride;
        }
        // Tail: strides 24,25,26 unconditional + 27 predicated, one batch.
        {
            float4 v0 = A4[i];
            float4 v1 = A4[i + stride];
            float4 v2 = A4[i + 2 * stride];
            const size_t i3 = i + 3 * stride;
            float4 v3 = (i3 < N4) ? A4[i3] : make_float4(0.f, 0.f, 0.f, 0.f);

            ax += (v0.x + v1.x) + (v2.x + v3.x);
            ay += (v0.y + v1.y) + (v2.y + v3.y);
            az += (v0.z + v1.z) + (v2.z + v3.z);
            aw += (v0.w + v1.w) + (v2.w + v3.w);
            sq = fmaf(v0.x, v0.x, sq); sq = fmaf(v0.y, v0.y, sq);
            sq = fmaf(v0.z, v0.z, sq); sq = fmaf(v0.w, v0.w, sq);
            sq = fmaf(v1.x, v1.x, sq); sq = fmaf(v1.y, v1.y, sq);
            sq = fmaf(v1.z, v1.z, sq); sq = fmaf(v1.w, v1.w, sq);
            sq = fmaf(v2.x, v2.x, sq); sq = fmaf(v2.y, v2.y, sq);
            sq = fmaf(v2.z, v2.z, sq); sq = fmaf(v2.w, v2.w, sq);
            sq = fmaf(v3.x, v3.x, sq); sq = fmaf(v3.y, v3.y, sq);
            sq = fmaf(v3.z, v3.z, sq); sq = fmaf(v3.w, v3.w, sq);
        }
    } else {
        // Generic grid-stride fallback.
        for (; i < N4; i += stride) {
            float4 v = A4[i];
            ax += v.x; ay += v.y; az += v.z; aw += v.w;
            sq = fmaf(v.x, v.x, sq); sq = fmaf(v.y, v.y, sq);
            sq = fmaf(v.z, v.z, sq); sq = fmaf(v.w, v.w, sq);
        }
    }

    // ---- combine the 4 phases via smem ----
    __shared__ float4 sc[4][D4];
    sc[rs][c4] = make_float4(ax, ay, az, aw);

    #pragma unroll
    for (int off = 16; off > 0; off >>= 1)
        sq += __shfl_xor_sync(0xFFFFFFFFu, sq, off);

    __shared__ float swarp[TPB / 32];
    if ((t & 31) == 0) swarp[t >> 5] = sq;
    __syncthreads();

    // ---- non-atomic partial write: private row per block ----
    float4* __restrict__ P4 = reinterpret_cast<float4*>(g_part);
    if (t < D4) {
        float4 s0 = sc[0][t], s1 = sc[1][t], s2 = sc[2][t], s3 = sc[3][t];
        float4 r;
        r.x = (s0.x + s1.x) + (s2.x + s3.x);
        r.y = (s0.y + s1.y) + (s2.y + s3.y);
        r.z = (s0.z + s1.z) + (s2.z + s3.z);
        r.w = (s0.w + s1.w) + (s2.w + s3.w);
        P4[blockIdx.x * D4 + t] = r;
    }
    if (t < TPB / 32) {
        float w = swarp[t];
        #pragma unroll
        for (int off = 8; off > 0; off >>= 1)
            w += __shfl_xor_sync(0xFFFFu, w, off);
        if (t == 0) g_sqpart[blockIdx.x] = w;
    }

    // ---- level 1: last block of each 4-block group folds the group ----
    const int grp = blockIdx.x >> 2;
    __syncthreads();                       // partial stores issued block-wide
    __shared__ int sh_glast;
    if (t == 0)
        sh_glast = (atom_inc_acqrel(&g_gcount[grp]) == 3u);
    __syncthreads();
    if (!sh_glast) return;

    {
        float s = 0.f;
        #pragma unroll
        for (int j = 0; j < 4; j++)
            s += g_part[(size_t)(grp * 4 + j) * D + t];
        g_gpart[(size_t)grp * D + t] = s;
        if (t == 0) {
            float qs = 0.f;
            #pragma unroll
            for (int j = 0; j < 4; j++) qs += g_sqpart[grp * 4 + j];
            g_gsq[grp] = qs;
        }
    }

    // ---- level 2: last group folds 37 group rows and finalizes ----
    __syncthreads();
    __shared__ int sh_flast;
    if (t == 0)
        sh_flast = (atom_inc_acqrel(&g_fcount) == NGROUPS - 1u);
    __syncthreads();
    if (!sh_flast) return;

    {
        float c = 0.f;
        #pragma unroll
        for (int g = 0; g < NGROUPS; g++)
            c += g_gpart[(size_t)g * D + t];

        float p = c * c;                               // ||colsum||^2 partial
        float q = (t < NGROUPS) ? g_gsq[t] : 0.f;
        float r = p - q;

        #pragma unroll
        for (int off = 16; off > 0; off >>= 1)
            r += __shfl_xor_sync(0xFFFFFFFFu, r, off);

        __shared__ float fwarp[TPB / 32];
        if ((t & 31) == 0) fwarp[t >> 5] = r;
        __syncthreads();

        // reset counters for the next graph replay
        if (t < NGROUPS) g_gcount[t] = 0u;

        if (t == 0) {
            float tot = 0.f;
            #pragma unroll
            for (int w = 0; w < TPB / 32; w++) tot += fwarp[w];
            double denom = (double)n_rows * (double)(n_rows - 1);
            out[0] = (float)((double)tot / denom);
            g_fcount = 0u;
        }
    }
}

extern "C" void kernel_launch(void* const* d_in, const int* in_sizes, int n_in,
                              void* d_out, int out_size) {
    const float* A = (const float*)d_in[0];
    const int n_rows = in_sizes[0] / D;   // 16384
    ddc2_kernel<<<GRID, TPB>>>(A, n_rows, (float*)d_out);
}